// round 13
// baseline (speedup 1.0000x reference)
#include <cuda_runtime.h>
#include <cstdint>

#define BB 8
#define NN 128
#define KK 16
#define NB (BB*NN)
#define JSPLIT 8
#define JCHUNK (NN/JSPLIT)   // 16
#define RPB 16               // rows per block in pairA

#define ALPHA_C 0.01f
#define LAM_C   1.0f
#define KAPPA_C 1.0f
#define EPSV    1e-6f

// scratch (device globals: no allocation allowed)
__device__ float g_E[NB * 256];          // E[bn] = expm(phi.G), row-major
__device__ float g_M[NB * 256];          // M[bn] = F diag(1/(sq+eps)) F^T (symmetric)
__device__ float g_w[NB * KK];           // w = F mu_q
__device__ float g_u[NB * KK];           // u = M w
__device__ float g_s1[JSPLIT * NB * KK]; // [split][bn][k]
__device__ float g_s2[JSPLIT * NB * KK];
__device__ float g_s3[JSPLIT * NB];

// ---------------------------------------------------------------------------
// 16x16 matmul step, thread = (i = t>>3, jd = t&7) owning C[i][2jd..2jd+1].
// T row hoisted into registers (4x LDS.128), inner: LDS.64 + 2 FMA per l.
// ---------------------------------------------------------------------------
__device__ __forceinline__ float2 mm2h(const float* __restrict__ Ts,
                                       const float* __restrict__ Bs,
                                       int i, int jd)
{
    float tr[16];
    #pragma unroll
    for (int q = 0; q < 4; q++) {
        const float4 v = *reinterpret_cast<const float4*>(Ts + i*16 + q*4);
        tr[q*4+0] = v.x; tr[q*4+1] = v.y; tr[q*4+2] = v.z; tr[q*4+3] = v.w;
    }
    float c0 = 0.f, c1 = 0.f;
    #pragma unroll
    for (int l = 0; l < 16; l++) {
        const float2 b = *reinterpret_cast<const float2*>(Bs + l*16 + jd*2);
        c0 = fmaf(tr[l], b.x, c0);
        c1 = fmaf(tr[l], b.y, c1);
    }
    return make_float2(c0, c1);
}

// dual matmul sharing one hoisted T row: C0 = T*B0, C1 = T*B1 (ILP x2)
__device__ __forceinline__ void mm2h2(const float* __restrict__ Ts,
                                      const float* __restrict__ B0,
                                      const float* __restrict__ B1,
                                      float2& o0, float2& o1, int i, int jd)
{
    float tr[16];
    #pragma unroll
    for (int q = 0; q < 4; q++) {
        const float4 v = *reinterpret_cast<const float4*>(Ts + i*16 + q*4);
        tr[q*4+0] = v.x; tr[q*4+1] = v.y; tr[q*4+2] = v.z; tr[q*4+3] = v.w;
    }
    float a0 = 0.f, a1 = 0.f, b0 = 0.f, b1 = 0.f;
    #pragma unroll
    for (int l = 0; l < 16; l++) {
        const float2 x = *reinterpret_cast<const float2*>(B0 + l*16 + jd*2);
        const float2 y = *reinterpret_cast<const float2*>(B1 + l*16 + jd*2);
        a0 = fmaf(tr[l], x.x, a0); a1 = fmaf(tr[l], x.y, a1);
        b0 = fmaf(tr[l], y.x, b0); b1 = fmaf(tr[l], y.y, b1);
    }
    o0 = make_float2(a0, a1);
    o1 = make_float2(b0, b1);
}

// ---------------------------------------------------------------------------
// Kernel 1: one matrix per 128-thread block (1024 blocks).
// expm via Paterson-Stockmeyer Taylor-13; sc from ||A^2||_inf (2-norm bound);
// then E, M, w, u, grad_sigma. ~9+sc block barriers.
// ---------------------------------------------------------------------------
__global__ void __launch_bounds__(128) prep_kernel(
    const float* __restrict__ mu_q,
    const float* __restrict__ sigma_q,
    const float* __restrict__ sigma_p,
    const float* __restrict__ phi,
    const float* __restrict__ gen,
    float* __restrict__ out_sigma)
{
    const int t  = threadIdx.x;
    const int i  = t >> 3;     // row 0..15
    const int jd = t & 7;      // col pair 0..7
    const int bn = blockIdx.x;
    const int base = i*16 + jd*2;

    __shared__ float bA[256], bX[256], bX2[256], bX3[256], bT0[256], bT1[256];
    __shared__ float sr[16], smu[16], srow[16];

    // ---- A = phi . G (this thread's 2 elements) ----
    const float p0 = __ldg(&phi[bn*3 + 0]);
    const float p1 = __ldg(&phi[bn*3 + 1]);
    const float p2 = __ldg(&phi[bn*3 + 2]);
    float a0 = p0*__ldg(&gen[base])   + p1*__ldg(&gen[256+base])   + p2*__ldg(&gen[512+base]);
    float a1 = p0*__ldg(&gen[base+1]) + p1*__ldg(&gen[256+base+1]) + p2*__ldg(&gen[512+base+1]);

    if (t < 16) {
        const float mu = mu_q[bn*KK + t];
        const float sq = fmaxf(sigma_q[bn*KK + t], EPSV);
        const float sp = fmaxf(sigma_p[bn*KK + t], EPSV);
        sr[t]  = 1.0f / (sq + EPSV);
        smu[t] = mu;
        out_sigma[bn*KK + t] = ALPHA_C * 0.5f * (1.0f/sp - 1.0f/sq);
    }

    bA[base] = a0; bA[base+1] = a1;
    __syncthreads();                                   // S1

    // ---- Xr = A^2 (unscaled); ||Xr||_inf bounds ||A||_2^2 ----
    float2 xr = mm2h(bA, bA, i, jd);
    float rs = fabsf(xr.x) + fabsf(xr.y);
    rs += __shfl_xor_sync(0xffffffffu, rs, 1);
    rs += __shfl_xor_sync(0xffffffffu, rs, 2);
    rs += __shfl_xor_sync(0xffffffffu, rs, 4);   // sum over jd
    if (jd == 0) srow[i] = rs;
    __syncthreads();                                   // S2

    float nX = 0.f;
    #pragma unroll
    for (int l = 0; l < 16; l++) nX = fmaxf(nX, srow[l]);

    int sc = 0;
    float tt = nX * 0.25f;                 // theta = 2
    while (tt > 1.0f && sc < 12) { sc++; tt *= 0.25f; }

    const float sA  = ldexpf(1.0f, -sc);
    const float sXc = sA * sA;
    a0 *= sA; a1 *= sA;
    const float x0 = xr.x * sXc, x1 = xr.y * sXc;

    bA[base] = a0; bA[base+1] = a1;
    bX[base] = x0; bX[base+1] = x1;
    __syncthreads();                                   // S3

    float2 x2 = mm2h(bX, bX, i, jd);                   // A^4
    bX2[base] = x2.x; bX2[base+1] = x2.y;
    __syncthreads();                                   // S4
    float2 x3 = mm2h(bX2, bX, i, jd);                  // A^6
    bX3[base] = x3.x; bX3[base+1] = x3.y;

    // Taylor-13 even/odd coefficients
    const float c1c = 1.f/2.f,      c2c = 1.f/24.f,      c3c = 1.f/720.f;
    const float c4c = 1.f/40320.f,  c5c = 1.f/3628800.f, c6c = 1.f/479001600.f;
    const float d1c = 1.f/6.f,      d2c = 1.f/120.f,     d3c = 1.f/5040.f;
    const float d4c = 1.f/362880.f, d5c = 1.f/39916800.f, d6c = 1.6059044e-10f; // 1/13!

    // stage both bracket temps, one barrier, dual mm
    bT0[base]   = fmaf(c4c, x0, fmaf(c5c, x2.x, c6c*x3.x));
    bT0[base+1] = fmaf(c4c, x1, fmaf(c5c, x2.y, c6c*x3.y));
    bT1[base]   = fmaf(d4c, x0, fmaf(d5c, x2.x, d6c*x3.x));
    bT1[base+1] = fmaf(d4c, x1, fmaf(d5c, x2.y, d6c*x3.y));
    __syncthreads();                                   // S5

    float2 pb, qb;
    mm2h2(bX3, bT0, bT1, pb, qb, i, jd);

    const int  dq = i - jd*2;                          // diag owned iff dq in {0,1}
    float P0 = fmaf(c1c, x0, fmaf(c2c, x2.x, fmaf(c3c, x3.x, pb.x)));
    float P1 = fmaf(c1c, x1, fmaf(c2c, x2.y, fmaf(c3c, x3.y, pb.y)));
    float Q0 = fmaf(d1c, x0, fmaf(d2c, x2.x, fmaf(d3c, x3.x, qb.x)));
    float Q1 = fmaf(d1c, x1, fmaf(d2c, x2.y, fmaf(d3c, x3.y, qb.y)));
    if (dq == 0) { P0 += 1.0f; Q0 += 1.0f; }
    if (dq == 1) { P1 += 1.0f; Q1 += 1.0f; }

    __syncthreads();                                   // S6 (bracket reads of bT0 done)
    bT0[base] = Q0; bT0[base+1] = Q1;
    __syncthreads();                                   // S7
    float2 aq = mm2h(bA, bT0, i, jd);                  // A*Q
    float R0 = aq.x + P0;
    float R1 = aq.y + P1;

    // ---- squarings: ping-pong bX / bX2 (dead after X3) ----
    float* pp[2] = { bX, bX2 };
    int cur = 0;
    for (int q = 0; q < sc; q++) {
        pp[cur][base] = R0; pp[cur][base+1] = R1;
        __syncthreads();
        float2 rr = mm2h(pp[cur], pp[cur], i, jd);
        R0 = rr.x; R1 = rr.y;
        cur ^= 1;
    }

    // ---- write E; stage E (bA) and S = E.*r_row (bX) ----
    *reinterpret_cast<float2*>(g_E + (size_t)bn*256 + base) = make_float2(R0, R1);
    __syncthreads();                                   // S8 (AQ-mm readers of bA done)
    const float sri = sr[i];
    bA[base] = R0;       bA[base+1] = R1;
    bX[base] = R0 * sri; bX[base+1] = R1 * sri;
    __syncthreads();                                   // S9

    // ---- M[i][2jd+q] = sum_l E[l][i] * S[l][2jd+q] ----
    {
        float m0 = 0.f, m1 = 0.f;
        #pragma unroll
        for (int l = 0; l < 16; l++) {
            const float e  = bA[l*16 + i];
            const float2 b = *reinterpret_cast<const float2*>(bX + l*16 + jd*2);
            m0 = fmaf(e, b.x, m0);
            m1 = fmaf(e, b.y, m1);
        }
        *reinterpret_cast<float2*>(g_M + (size_t)bn*256 + base) = make_float2(m0, m1);
    }

    // ---- w[k] = sum_l E[l][k] mu[l];  u[k] = sum_l S[l][k] mu[l] ----
    if (t < 16) {
        float wacc = 0.f, uacc = 0.f;
        #pragma unroll
        for (int l = 0; l < 16; l++) {
            const float m = smu[l];
            wacc = fmaf(bA[l*16 + t], m, wacc);
            uacc = fmaf(bX[l*16 + t], m, uacc);
        }
        g_w[bn*KK + t] = wacc;
        g_u[bn*KK + t] = uacc;
    }
}

// ---------------------------------------------------------------------------
// Kernel 2 (phase A): partial j-sums. Grid (JSPLIT, NB/RPB), 256 threads =
// 16 groups of 16 lanes (one row each); 16 rows share the staged chunk.
// (Proven R9 configuration: 512 blocks, 4096 warps.)
// ---------------------------------------------------------------------------
__global__ void __launch_bounds__(256) pairA_kernel(
    const float* __restrict__ beta)
{
    __shared__ float sM[JCHUNK * 256];   // 16 KB
    __shared__ float swv[JCHUNK * 16];
    __shared__ float suv[JCHUNK * 16];

    const int tid   = threadIdx.x;
    const int g     = tid >> 4;
    const int lane  = tid & 15;
    const int split = blockIdx.x;
    const int bn    = blockIdx.y * RPB + g;
    const int b     = bn >> 7;
    const int irow  = bn & 127;
    const int j0    = split * JCHUNK;

    {
        const float4* src = reinterpret_cast<const float4*>(g_M + (size_t)(b*NN + j0) * 256);
        float4* dst = reinterpret_cast<float4*>(sM);
        #pragma unroll
        for (int q = 0; q < 4; q++) dst[q*256 + tid] = src[q*256 + tid];
        swv[tid] = g_w[(size_t)(b*NN + j0) * KK + tid];
        suv[tid] = g_u[(size_t)(b*NN + j0) * KK + tid];
    }

    float wir[16];
    {
        const float4* wp = reinterpret_cast<const float4*>(g_w + (size_t)bn * KK);
        #pragma unroll
        for (int q = 0; q < 4; q++) {
            const float4 v4 = wp[q];
            wir[q*4+0] = v4.x; wir[q*4+1] = v4.y; wir[q*4+2] = v4.z; wir[q*4+3] = v4.w;
        }
    }
    const float wi_self = g_w[(size_t)bn*KK + lane];
    const float* __restrict__ betarow = beta + (size_t)(b*NN + irow) * NN + j0;

    __syncthreads();

    float s1 = 0.f, s2 = 0.f, s3 = 0.f;

    #pragma unroll
    for (int jj = 0; jj < JCHUNK; jj++) {
        const float* __restrict__ Mc = sM + jj*256;   // symmetric
        float z0 = 0.f, z1 = 0.f;
        #pragma unroll
        for (int l = 0; l < 16; l += 2) {
            z0 = fmaf(Mc[ l     *16 + lane], wir[l    ], z0);
            z1 = fmaf(Mc[(l + 1)*16 + lane], wir[l + 1], z1);
        }
        const float y = (z0 + z1) - suv[jj*16 + lane];
        const float d = wi_self   - swv[jj*16 + lane];

        float tt = d * y;
        tt += __shfl_xor_sync(0xffffffffu, tt, 1);
        tt += __shfl_xor_sync(0xffffffffu, tt, 2);
        tt += __shfl_xor_sync(0xffffffffu, tt, 4);
        tt += __shfl_xor_sync(0xffffffffu, tt, 8);
        const float kl  = 0.5f * tt;
        const float bij = __ldg(betarow + jj);
        const float klb = kl * bij;

        s1 = fmaf(bij, y, s1);
        s2 = fmaf(klb, y, s2);
        s3 += klb;
    }

    const int idx = split * (NB*KK) + bn*KK + lane;
    g_s1[idx] = s1;
    g_s2[idx] = s2;
    if (lane == 0) g_s3[split * NB + bn] = s3;
}

// ---------------------------------------------------------------------------
// Kernel 3: combine splits, rotate by E_i, add self term.
// ---------------------------------------------------------------------------
__global__ void __launch_bounds__(256) finish_kernel(
    const float* __restrict__ mu_q,
    const float* __restrict__ mu_p,
    const float* __restrict__ sigma_p,
    float* __restrict__ out_mu)
{
    const int tid  = threadIdx.x;
    const int g    = tid >> 4;
    const int lane = tid & 15;
    const int bn   = blockIdx.x * 16 + g;

    float s1 = 0.f, s2 = 0.f, s3 = 0.f;
    #pragma unroll
    for (int s = 0; s < JSPLIT; s++) {
        s1 += g_s1[((size_t)s*NB + bn)*KK + lane];
        s2 += g_s2[((size_t)s*NB + bn)*KK + lane];
        s3 += g_s3[s*NB + bn];
    }
    const float v = LAM_C * s1 + (LAM_C / KAPPA_C) * (s2 - s3 * s1);

    float er[16];
    {
        const float4* ep = reinterpret_cast<const float4*>(g_E + (size_t)bn*256 + lane*16);
        #pragma unroll
        for (int q = 0; q < 4; q++) {
            const float4 t4 = ep[q];
            er[q*4+0] = t4.x; er[q*4+1] = t4.y; er[q*4+2] = t4.z; er[q*4+3] = t4.w;
        }
    }
    float o = 0.f;
    #pragma unroll
    for (int l = 0; l < 16; l++)
        o = fmaf(er[l], __shfl_sync(0xffffffffu, v, l, 16), o);

    const float sp   = fmaxf(sigma_p[bn*KK + lane], EPSV);
    const float self = ALPHA_C * (mu_q[bn*KK + lane] - mu_p[bn*KK + lane]) / sp;

    out_mu[bn*KK + lane] = self + o;
}

// ---------------------------------------------------------------------------
extern "C" void kernel_launch(void* const* d_in, const int* in_sizes, int n_in,
                              void* d_out, int out_size)
{
    const float* mu_q    = (const float*)d_in[0];
    const float* sigma_q = (const float*)d_in[1];
    const float* mu_p    = (const float*)d_in[2];
    const float* sigma_p = (const float*)d_in[3];
    const float* beta    = (const float*)d_in[4];
    const float* phi     = (const float*)d_in[5];
    const float* gen     = (const float*)d_in[6];

    float* out       = (float*)d_out;
    float* out_mu    = out;            // (B,N,K)
    float* out_sigma = out + NB*KK;    // (B,N,K)

    prep_kernel<<<NB, 128>>>(mu_q, sigma_q, sigma_p, phi, gen, out_sigma);
    pairA_kernel<<<dim3(JSPLIT, NB/RPB), 256>>>(beta);
    finish_kernel<<<NB/16, 256>>>(mu_q, mu_p, sigma_p, out_mu);
}